// round 1
// baseline (speedup 1.0000x reference)
#include <cuda_runtime.h>
#include <math.h>

// Problem constants
#define PB 4
#define PC 2048
#define PE 1024
#define PH 16
#define PHD 64
#define PM (PB*PC)        // 8192
#define PK PE             // 1024
#define PN3 (3*PE)        // 3072

// Scratch (device globals: allocation-free rule)
__device__ float g_q[(size_t)PB*PH*PC*PHD];
__device__ float g_k[(size_t)PB*PH*PC*PHD];
__device__ float g_v[(size_t)PB*PH*PC*PHD];
__device__ float g_y[(size_t)PM*PE];

// ---------------------------------------------------------------------------
// SGEMM: 128x128 tile, BK=8, 256 threads, 8x8 per thread
// ---------------------------------------------------------------------------
__global__ __launch_bounds__(256, 2)
void qkv_gemm_kernel(const float* __restrict__ A, const float* __restrict__ B)
{
    const int K = PK, N = PN3;
    __shared__ float As[8][128];
    __shared__ float Bs[8][128];

    int tid = threadIdx.x;
    int bx = blockIdx.x, by = blockIdx.y;
    int ty = tid >> 4, tx = tid & 15;

    int arow = tid >> 1,        acol = (tid & 1) << 2;
    int brow = tid >> 5,        bcol = (tid & 31) << 2;

    const float* Ap = A + (size_t)(by * 128 + arow) * K + acol;
    const float* Bp = B + (size_t)brow * N + bx * 128 + bcol;

    float acc[8][8];
    #pragma unroll
    for (int i = 0; i < 8; i++)
        #pragma unroll
        for (int j = 0; j < 8; j++) acc[i][j] = 0.f;

    for (int k0 = 0; k0 < K; k0 += 8) {
        float4 a4 = *(const float4*)(Ap + k0);
        float4 b4 = *(const float4*)(Bp + (size_t)k0 * N);
        As[acol + 0][arow] = a4.x;
        As[acol + 1][arow] = a4.y;
        As[acol + 2][arow] = a4.z;
        As[acol + 3][arow] = a4.w;
        *(float4*)&Bs[brow][bcol] = b4;
        __syncthreads();

        #pragma unroll
        for (int kk = 0; kk < 8; kk++) {
            float ar[8], br[8];
            *(float4*)(ar)     = *(const float4*)&As[kk][ty * 8];
            *(float4*)(ar + 4) = *(const float4*)&As[kk][ty * 8 + 4];
            *(float4*)(br)     = *(const float4*)&Bs[kk][tx * 8];
            *(float4*)(br + 4) = *(const float4*)&Bs[kk][tx * 8 + 4];
            #pragma unroll
            for (int i = 0; i < 8; i++)
                #pragma unroll
                for (int j = 0; j < 8; j++)
                    acc[i][j] = fmaf(ar[i], br[j], acc[i][j]);
        }
        __syncthreads();
    }

    // Epilogue: scatter into head-major q/k/v [B,H,C,HD]
    int n0 = bx * 128 + tx * 8;       // 8 contiguous n, same (which, head)
    int which = n0 >> 10;
    int hn = n0 & 1023;
    int h = hn >> 6;
    int d0 = hn & 63;                 // multiple of 8
    float* dst = (which == 0) ? g_q : (which == 1 ? g_k : g_v);

    #pragma unroll
    for (int i = 0; i < 8; i++) {
        int m = by * 128 + ty * 8 + i;
        int b = m >> 11, c = m & 2047;
        size_t base = (((size_t)(b * PH + h)) * PC + c) * PHD + d0;
        *(float4*)&dst[base]     = *(float4*)&acc[i][0];
        *(float4*)&dst[base + 4] = *(float4*)&acc[i][4];
    }
}

__global__ __launch_bounds__(256, 2)
void proj_gemm_kernel(const float* __restrict__ B, float* __restrict__ Cout)
{
    const int K = PK, N = PE;
    const float* A = g_y;
    __shared__ float As[8][128];
    __shared__ float Bs[8][128];

    int tid = threadIdx.x;
    int bx = blockIdx.x, by = blockIdx.y;
    int ty = tid >> 4, tx = tid & 15;

    int arow = tid >> 1,  acol = (tid & 1) << 2;
    int brow = tid >> 5,  bcol = (tid & 31) << 2;

    const float* Ap = A + (size_t)(by * 128 + arow) * K + acol;
    const float* Bp = B + (size_t)brow * N + bx * 128 + bcol;

    float acc[8][8];
    #pragma unroll
    for (int i = 0; i < 8; i++)
        #pragma unroll
        for (int j = 0; j < 8; j++) acc[i][j] = 0.f;

    for (int k0 = 0; k0 < K; k0 += 8) {
        float4 a4 = *(const float4*)(Ap + k0);
        float4 b4 = *(const float4*)(Bp + (size_t)k0 * N);
        As[acol + 0][arow] = a4.x;
        As[acol + 1][arow] = a4.y;
        As[acol + 2][arow] = a4.z;
        As[acol + 3][arow] = a4.w;
        *(float4*)&Bs[brow][bcol] = b4;
        __syncthreads();

        #pragma unroll
        for (int kk = 0; kk < 8; kk++) {
            float ar[8], br[8];
            *(float4*)(ar)     = *(const float4*)&As[kk][ty * 8];
            *(float4*)(ar + 4) = *(const float4*)&As[kk][ty * 8 + 4];
            *(float4*)(br)     = *(const float4*)&Bs[kk][tx * 8];
            *(float4*)(br + 4) = *(const float4*)&Bs[kk][tx * 8 + 4];
            #pragma unroll
            for (int i = 0; i < 8; i++)
                #pragma unroll
                for (int j = 0; j < 8; j++)
                    acc[i][j] = fmaf(ar[i], br[j], acc[i][j]);
        }
        __syncthreads();
    }

    #pragma unroll
    for (int i = 0; i < 8; i++) {
        size_t m = by * 128 + ty * 8 + i;
        size_t n = bx * 128 + tx * 8;
        *(float4*)&Cout[m * N + n]     = *(float4*)&acc[i][0];
        *(float4*)&Cout[m * N + n + 4] = *(float4*)&acc[i][4];
    }
}

// ---------------------------------------------------------------------------
// Flash attention: CTA = (qblock of 64 rows, b*h). 256 thr, 16x16 -> 4x4 frags
// ---------------------------------------------------------------------------
#define APITCH 68   // row pitch (floats), 16B-aligned, avoids worst conflicts
#define ASMEM_FLOATS (4 * 64 * APITCH)

__global__ __launch_bounds__(256, 1)
void attn_kernel()
{
    extern __shared__ float smem[];
    float* Qs = smem;                        // 64 x APITCH (pre-scaled by 1/8)
    float* Ks = Qs + 64 * APITCH;
    float* Vs = Ks + 64 * APITCH;
    float* Ps = Vs + 64 * APITCH;

    const int qb = blockIdx.x;               // 0..31
    const int bh = blockIdx.y;               // 0..63
    const float* Qbase = g_q + (size_t)bh * PC * PHD;
    const float* Kbase = g_k + (size_t)bh * PC * PHD;
    const float* Vbase = g_v + (size_t)bh * PC * PHD;

    const int tid = threadIdx.x;
    const int ty = tid >> 4, tx = tid & 15;

    // Load Q tile (scaled by 1/sqrt(64) = 0.125)
    for (int i = tid; i < 64 * 16; i += 256) {
        int r = i >> 4, c4 = (i & 15) << 2;
        float4 v = *(const float4*)(Qbase + (size_t)(qb * 64 + r) * PHD + c4);
        float* q = &Qs[r * APITCH + c4];
        q[0] = v.x * 0.125f; q[1] = v.y * 0.125f;
        q[2] = v.z * 0.125f; q[3] = v.w * 0.125f;
    }

    float o[4][4];
    float m_r[4], l_r[4];
    #pragma unroll
    for (int i = 0; i < 4; i++) {
        m_r[i] = -1e30f; l_r[i] = 0.f;
        #pragma unroll
        for (int j = 0; j < 4; j++) o[i][j] = 0.f;
    }
    __syncthreads();

    for (int jb = 0; jb <= qb; jb++) {
        // Load K, V tiles
        for (int i = tid; i < 64 * 16; i += 256) {
            int r = i >> 4, c4 = (i & 15) << 2;
            *(float4*)&Ks[r * APITCH + c4] =
                *(const float4*)(Kbase + (size_t)(jb * 64 + r) * PHD + c4);
            *(float4*)&Vs[r * APITCH + c4] =
                *(const float4*)(Vbase + (size_t)(jb * 64 + r) * PHD + c4);
        }
        __syncthreads();

        // S = Q K^T  (4x4 fragment per thread)
        float s[4][4];
        #pragma unroll
        for (int i = 0; i < 4; i++)
            #pragma unroll
            for (int j = 0; j < 4; j++) s[i][j] = 0.f;

        #pragma unroll
        for (int d = 0; d < 64; d += 4) {
            float4 q4[4], k4[4];
            #pragma unroll
            for (int i = 0; i < 4; i++)
                q4[i] = *(const float4*)&Qs[(ty * 4 + i) * APITCH + d];
            #pragma unroll
            for (int j = 0; j < 4; j++)
                k4[j] = *(const float4*)&Ks[(tx * 4 + j) * APITCH + d];
            #pragma unroll
            for (int i = 0; i < 4; i++)
                #pragma unroll
                for (int j = 0; j < 4; j++) {
                    s[i][j] = fmaf(q4[i].x, k4[j].x, s[i][j]);
                    s[i][j] = fmaf(q4[i].y, k4[j].y, s[i][j]);
                    s[i][j] = fmaf(q4[i].z, k4[j].z, s[i][j]);
                    s[i][j] = fmaf(q4[i].w, k4[j].w, s[i][j]);
                }
        }

        // Causal mask (only diagonal block is partial)
        if (jb == qb) {
            #pragma unroll
            for (int i = 0; i < 4; i++) {
                int qrow = ty * 4 + i;
                #pragma unroll
                for (int j = 0; j < 4; j++) {
                    if (tx * 4 + j > qrow) s[i][j] = -1e30f;
                }
            }
        }

        // Online softmax update
        #pragma unroll
        for (int i = 0; i < 4; i++) {
            float rmax = fmaxf(fmaxf(s[i][0], s[i][1]), fmaxf(s[i][2], s[i][3]));
            #pragma unroll
            for (int off = 8; off > 0; off >>= 1)
                rmax = fmaxf(rmax, __shfl_xor_sync(0xffffffffu, rmax, off));
            float new_m = fmaxf(m_r[i], rmax);
            float alpha = __expf(m_r[i] - new_m);
            float rsum = 0.f;
            #pragma unroll
            for (int j = 0; j < 4; j++) {
                float p = __expf(s[i][j] - new_m);
                s[i][j] = p;                  // reuse s[][] as P
                rsum += p;
            }
            #pragma unroll
            for (int off = 8; off > 0; off >>= 1)
                rsum += __shfl_xor_sync(0xffffffffu, rsum, off);
            l_r[i] = l_r[i] * alpha + rsum;
            m_r[i] = new_m;
            #pragma unroll
            for (int j = 0; j < 4; j++) o[i][j] *= alpha;
        }

        // Stage P in smem
        #pragma unroll
        for (int i = 0; i < 4; i++)
            #pragma unroll
            for (int j = 0; j < 4; j++)
                Ps[(ty * 4 + i) * APITCH + tx * 4 + j] = s[i][j];
        __syncthreads();

        // O += P @ V
        #pragma unroll 16
        for (int kk = 0; kk < 64; kk++) {
            float4 vv = *(const float4*)&Vs[kk * APITCH + tx * 4];
            #pragma unroll
            for (int i = 0; i < 4; i++) {
                float pf = Ps[(ty * 4 + i) * APITCH + kk];
                o[i][0] = fmaf(pf, vv.x, o[i][0]);
                o[i][1] = fmaf(pf, vv.y, o[i][1]);
                o[i][2] = fmaf(pf, vv.z, o[i][2]);
                o[i][3] = fmaf(pf, vv.w, o[i][3]);
            }
        }
        __syncthreads();
    }

    // Write y in [B,C,E] with e = h*64 + d
    int b = bh >> 4, h = bh & 15;
    #pragma unroll
    for (int i = 0; i < 4; i++) {
        float inv_l = 1.0f / l_r[i];
        int qg = qb * 64 + ty * 4 + i;
        size_t base = ((size_t)b * PC + qg) * PE + h * PHD + tx * 4;
        float4 ov;
        ov.x = o[i][0] * inv_l; ov.y = o[i][1] * inv_l;
        ov.z = o[i][2] * inv_l; ov.w = o[i][3] * inv_l;
        *(float4*)&g_y[base] = ov;
    }
}

// ---------------------------------------------------------------------------
extern "C" void kernel_launch(void* const* d_in, const int* in_sizes, int n_in,
                              void* d_out, int out_size)
{
    const float* x  = (const float*)d_in[0];
    const float* Wa = (const float*)d_in[1];
    const float* Wp = (const float*)d_in[2];
    float* out = (float*)d_out;

    dim3 g1(PN3 / 128, PM / 128);       // 24 x 64
    qkv_gemm_kernel<<<g1, 256>>>(x, Wa);

    static int smem_set = 0;
    size_t smem_bytes = ASMEM_FLOATS * sizeof(float);   // ~69.6 KB
    if (!smem_set) {
        cudaFuncSetAttribute(attn_kernel,
                             cudaFuncAttributeMaxDynamicSharedMemorySize,
                             (int)smem_bytes);
        smem_set = 1;
    }
    attn_kernel<<<dim3(PC / 64, PB * PH), 256, smem_bytes>>>();

    dim3 g2(PE / 128, PM / 128);        // 8 x 64
    proj_gemm_kernel<<<g2, 256>>>(Wp, out);
}

// round 2
// speedup vs baseline: 4.3740x; 4.3740x over previous
#include <cuda_runtime.h>
#include <cstdint>

#define PB 4
#define PC 2048
#define PE 1024
#define PH 16
#define PHD 64
#define PM (PB*PC)        // 8192
#define PK PE             // 1024
#define PN3 (3*PE)        // 3072

// Scratch (device globals: allocation-free rule)
__device__ float g_q[(size_t)PB*PH*PC*PHD];
__device__ float g_k[(size_t)PB*PH*PC*PHD];
__device__ float g_v[(size_t)PB*PH*PC*PHD];
__device__ float g_y[(size_t)PM*PE];

// ---------------------------------------------------------------------------
// Helpers
// ---------------------------------------------------------------------------
__device__ __forceinline__ uint32_t f2t(float x) {
    uint32_t r;
    asm("cvt.rna.tf32.f32 %0, %1;" : "=r"(r) : "f"(x));
    return r;
}

__device__ __forceinline__ void mma_tf32(float* c, const uint32_t* a, const uint32_t* b) {
    asm volatile(
        "mma.sync.aligned.m16n8k8.row.col.f32.tf32.tf32.f32 "
        "{%0,%1,%2,%3}, {%4,%5,%6,%7}, {%8,%9}, {%0,%1,%2,%3};"
        : "+f"(c[0]), "+f"(c[1]), "+f"(c[2]), "+f"(c[3])
        : "r"(a[0]), "r"(a[1]), "r"(a[2]), "r"(a[3]), "r"(b[0]), "r"(b[1]));
}

__device__ __forceinline__ void cp16(void* smem_dst, const void* gsrc) {
    uint32_t d = (uint32_t)__cvta_generic_to_shared(smem_dst);
    asm volatile("cp.async.cg.shared.global [%0], [%1], 16;" :: "r"(d), "l"(gsrc));
}
__device__ __forceinline__ void cp_commit() {
    asm volatile("cp.async.commit_group;");
}
template<int N> __device__ __forceinline__ void cp_wait() {
    asm volatile("cp.async.wait_group %0;" :: "n"(N));
}

// ---------------------------------------------------------------------------
// TF32 GEMM: 128x128x32 CTA tile, 8 warps, warp tile 64x32, m16n8k8
// As layout [m][k], pitch 36 (4 mod 32 -> conflict-free A-frag loads)
// Bs layout [k][n], pitch 136 (8 mod 32 -> conflict-free B-frag loads)
// EPI 0: qkv scatter to g_q/g_k/g_v head-major; EPI 1: plain C write
// ---------------------------------------------------------------------------
#define APITCH 36
#define BPITCH 136
#define ASZ (128*APITCH)
#define BSZ (32*BPITCH)

template<int N, int EPI>
__global__ __launch_bounds__(256, 2)
void gemm_tf32(const float* __restrict__ A, const float* __restrict__ Bm,
               float* __restrict__ Cout)
{
    extern __shared__ float sm[];
    float* As = sm;               // 2 * ASZ
    float* Bs = sm + 2 * ASZ;     // 2 * BSZ

    const int K = PK;
    const float* Ap = (EPI == 1) ? (const float*)g_y : A;

    const int tid = threadIdx.x;
    const int warp = tid >> 5, lane = tid & 31;
    const int l4 = lane >> 2, lq = lane & 3;
    const int wm = (warp & 1) * 64, wn = (warp >> 1) * 32;
    const int bx = blockIdx.x, by = blockIdx.y;

    float acc[4][4][4];
    #pragma unroll
    for (int i = 0; i < 4; i++)
        #pragma unroll
        for (int j = 0; j < 4; j++)
            #pragma unroll
            for (int r = 0; r < 4; r++) acc[i][j][r] = 0.f;

    auto issue = [&](int it) {
        int buf = it & 1;
        int k0 = it * 32;
        float* Ab = As + buf * ASZ;
        float* Bb = Bs + buf * BSZ;
        #pragma unroll
        for (int i = 0; i < 4; i++) {
            int idx = tid + i * 256;
            int r = idx >> 3, c4 = (idx & 7) * 4;
            cp16(Ab + r * APITCH + c4, Ap + (size_t)(by * 128 + r) * K + k0 + c4);
        }
        #pragma unroll
        for (int i = 0; i < 4; i++) {
            int idx = tid + i * 256;
            int kr = idx >> 5, c4 = (idx & 31) * 4;
            cp16(Bb + kr * BPITCH + c4, Bm + (size_t)(k0 + kr) * N + bx * 128 + c4);
        }
        cp_commit();
    };

    issue(0);
    const int NIT = K / 32;
    #pragma unroll 1
    for (int it = 0; it < NIT; ++it) {
        if (it + 1 < NIT) { issue(it + 1); cp_wait<1>(); }
        else              { cp_wait<0>(); }
        __syncthreads();
        const float* Ab = As + (it & 1) * ASZ;
        const float* Bb = Bs + (it & 1) * BSZ;

        #pragma unroll
        for (int ks = 0; ks < 4; ks++) {
            int k = ks * 8;
            uint32_t a[4][4], b[4][2];
            #pragma unroll
            for (int mt = 0; mt < 4; mt++) {
                int m = wm + mt * 16 + l4;
                a[mt][0] = f2t(Ab[m * APITCH + k + lq]);
                a[mt][1] = f2t(Ab[(m + 8) * APITCH + k + lq]);
                a[mt][2] = f2t(Ab[m * APITCH + k + 4 + lq]);
                a[mt][3] = f2t(Ab[(m + 8) * APITCH + k + 4 + lq]);
            }
            #pragma unroll
            for (int nt = 0; nt < 4; nt++) {
                int n = wn + nt * 8 + l4;
                b[nt][0] = f2t(Bb[(k + lq) * BPITCH + n]);
                b[nt][1] = f2t(Bb[(k + 4 + lq) * BPITCH + n]);
            }
            #pragma unroll
            for (int mt = 0; mt < 4; mt++)
                #pragma unroll
                for (int nt = 0; nt < 4; nt++)
                    mma_tf32(acc[mt][nt], a[mt], b[nt]);
        }
        __syncthreads();
    }

    // Epilogue
    #pragma unroll
    for (int mt = 0; mt < 4; mt++) {
        #pragma unroll
        for (int nt = 0; nt < 4; nt++) {
            int gm = by * 128 + wm + mt * 16 + l4;
            int gn = bx * 128 + wn + nt * 8 + lq * 2;
            if (EPI == 0) {
                int which = gn >> 10;
                int hn = gn & 1023;
                int h = hn >> 6, d = hn & 63;
                float* dst = (which == 0) ? g_q : (which == 1 ? g_k : g_v);
                int b_ = gm >> 11, c_ = gm & 2047;
                size_t base = (((size_t)(b_ * PH + h)) * PC + c_) * PHD + d;
                *(float2*)&dst[base] = make_float2(acc[mt][nt][0], acc[mt][nt][1]);
                *(float2*)&dst[base + (size_t)8 * PHD] =
                    make_float2(acc[mt][nt][2], acc[mt][nt][3]);
            } else {
                *(float2*)&Cout[(size_t)gm * N + gn] =
                    make_float2(acc[mt][nt][0], acc[mt][nt][1]);
                *(float2*)&Cout[(size_t)(gm + 8) * N + gn] =
                    make_float2(acc[mt][nt][2], acc[mt][nt][3]);
            }
        }
    }
}

// ---------------------------------------------------------------------------
// Flash attention (tf32 mma): CTA = 64 q-rows x (b*h). 4 warps, each m16.
// Qs/Ks pitch 68 (4 mod 32), Vs pitch 72 (8 mod 32) -> conflict-free frags.
// ---------------------------------------------------------------------------
#define QKP 68
#define VP  72
#define QS_SZ (64*QKP)
#define VS_SZ (64*VP)

__global__ __launch_bounds__(128, 2)
void attn_tf32()
{
    extern __shared__ float sm[];
    float* Qs = sm;                       // 64*QKP
    float* Ks = Qs + QS_SZ;               // 2 * 64*QKP
    float* Vs = Ks + 2 * QS_SZ;           // 2 * 64*VP

    const int qb = (int)gridDim.x - 1 - (int)blockIdx.x;   // big work first
    const int bh = blockIdx.y;
    const float* Qg = g_q + (size_t)bh * PC * PHD + (size_t)qb * 64 * PHD;
    const float* Kg = g_k + (size_t)bh * PC * PHD;
    const float* Vg = g_v + (size_t)bh * PC * PHD;

    const int tid = threadIdx.x;
    const int warp = tid >> 5, lane = tid & 31;
    const int l4 = lane >> 2, lq = lane & 3;
    const int mrow = warp * 16;

    // Load Q tile (plain loads; visibility covered by first pipeline barrier)
    #pragma unroll
    for (int i = 0; i < 8; i++) {
        int idx = tid + i * 128;
        int r = idx >> 4, c4 = (idx & 15) * 4;
        *(float4*)&Qs[r * QKP + c4] = *(const float4*)(Qg + r * 64 + c4);
    }

    auto issueKV = [&](int jb) {
        int buf = jb & 1;
        float* Kb = Ks + buf * QS_SZ;
        float* Vb = Vs + buf * VS_SZ;
        const float* kg = Kg + (size_t)jb * 64 * 64;
        const float* vg = Vg + (size_t)jb * 64 * 64;
        #pragma unroll
        for (int i = 0; i < 8; i++) {
            int idx = tid + i * 128;
            int r = idx >> 4, c4 = (idx & 15) * 4;
            cp16(Kb + r * QKP + c4, kg + r * 64 + c4);
            cp16(Vb + r * VP + c4, vg + r * 64 + c4);
        }
        cp_commit();
    };

    float o[8][4];
    #pragma unroll
    for (int nt = 0; nt < 8; nt++)
        #pragma unroll
        for (int j = 0; j < 4; j++) o[nt][j] = 0.f;
    float mx0 = -1e30f, mx1 = -1e30f, ls0 = 0.f, ls1 = 0.f;

    issueKV(0);

    #pragma unroll 1
    for (int jb = 0; jb <= qb; ++jb) {
        if (jb + 1 <= qb) { issueKV(jb + 1); cp_wait<1>(); }
        else              { cp_wait<0>(); }
        __syncthreads();
        const float* Kb = Ks + (jb & 1) * QS_SZ;
        const float* Vb = Vs + (jb & 1) * VS_SZ;

        // S = Q K^T
        float s[8][4];
        #pragma unroll
        for (int nt = 0; nt < 8; nt++)
            #pragma unroll
            for (int j = 0; j < 4; j++) s[nt][j] = 0.f;

        #pragma unroll
        for (int kt = 0; kt < 8; kt++) {
            int k = kt * 8;
            uint32_t a[4];
            a[0] = f2t(Qs[(mrow + l4) * QKP + k + lq]);
            a[1] = f2t(Qs[(mrow + 8 + l4) * QKP + k + lq]);
            a[2] = f2t(Qs[(mrow + l4) * QKP + k + 4 + lq]);
            a[3] = f2t(Qs[(mrow + 8 + l4) * QKP + k + 4 + lq]);
            #pragma unroll
            for (int nt = 0; nt < 8; nt++) {
                uint32_t b[2];
                b[0] = f2t(Kb[(nt * 8 + l4) * QKP + k + lq]);
                b[1] = f2t(Kb[(nt * 8 + l4) * QKP + k + 4 + lq]);
                mma_tf32(s[nt], a, b);
            }
        }

        // scale + causal mask
        #pragma unroll
        for (int nt = 0; nt < 8; nt++)
            #pragma unroll
            for (int j = 0; j < 4; j++) s[nt][j] *= 0.125f;

        if (jb == qb) {
            int r0 = mrow + l4, r1 = r0 + 8;
            #pragma unroll
            for (int nt = 0; nt < 8; nt++) {
                int cn = nt * 8 + lq * 2;
                if (cn     > r0) s[nt][0] = -1e30f;
                if (cn + 1 > r0) s[nt][1] = -1e30f;
                if (cn     > r1) s[nt][2] = -1e30f;
                if (cn + 1 > r1) s[nt][3] = -1e30f;
            }
        }

        // online softmax (rows r0 = mrow+l4, r1 = r0+8)
        float rm0 = -1e30f, rm1 = -1e30f;
        #pragma unroll
        for (int nt = 0; nt < 8; nt++) {
            rm0 = fmaxf(rm0, fmaxf(s[nt][0], s[nt][1]));
            rm1 = fmaxf(rm1, fmaxf(s[nt][2], s[nt][3]));
        }
        rm0 = fmaxf(rm0, __shfl_xor_sync(0xffffffffu, rm0, 1));
        rm0 = fmaxf(rm0, __shfl_xor_sync(0xffffffffu, rm0, 2));
        rm1 = fmaxf(rm1, __shfl_xor_sync(0xffffffffu, rm1, 1));
        rm1 = fmaxf(rm1, __shfl_xor_sync(0xffffffffu, rm1, 2));
        float nm0 = fmaxf(mx0, rm0), nm1 = fmaxf(mx1, rm1);
        float al0 = __expf(mx0 - nm0), al1 = __expf(mx1 - nm1);
        float rs0 = 0.f, rs1 = 0.f;
        #pragma unroll
        for (int nt = 0; nt < 8; nt++) {
            s[nt][0] = __expf(s[nt][0] - nm0); rs0 += s[nt][0];
            s[nt][1] = __expf(s[nt][1] - nm0); rs0 += s[nt][1];
            s[nt][2] = __expf(s[nt][2] - nm1); rs1 += s[nt][2];
            s[nt][3] = __expf(s[nt][3] - nm1); rs1 += s[nt][3];
        }
        rs0 += __shfl_xor_sync(0xffffffffu, rs0, 1);
        rs0 += __shfl_xor_sync(0xffffffffu, rs0, 2);
        rs1 += __shfl_xor_sync(0xffffffffu, rs1, 1);
        rs1 += __shfl_xor_sync(0xffffffffu, rs1, 2);
        ls0 = ls0 * al0 + rs0; mx0 = nm0;
        ls1 = ls1 * al1 + rs1; mx1 = nm1;
        #pragma unroll
        for (int nt = 0; nt < 8; nt++) {
            o[nt][0] *= al0; o[nt][1] *= al0;
            o[nt][2] *= al1; o[nt][3] *= al1;
        }

        // O += P @ V  (P shuffled from C-layout to A-layout within quads)
        #pragma unroll
        for (int kt = 0; kt < 8; kt++) {
            int src0 = (lane & ~3) | (lq >> 1);
            int src1 = src0 + 2;
            float v00 = __shfl_sync(0xffffffffu, s[kt][0], src0);
            float v01 = __shfl_sync(0xffffffffu, s[kt][1], src0);
            float v10 = __shfl_sync(0xffffffffu, s[kt][2], src0);
            float v11 = __shfl_sync(0xffffffffu, s[kt][3], src0);
            float w00 = __shfl_sync(0xffffffffu, s[kt][0], src1);
            float w01 = __shfl_sync(0xffffffffu, s[kt][1], src1);
            float w10 = __shfl_sync(0xffffffffu, s[kt][2], src1);
            float w11 = __shfl_sync(0xffffffffu, s[kt][3], src1);
            bool odd = (lq & 1);
            uint32_t a[4];
            a[0] = f2t(odd ? v01 : v00);
            a[1] = f2t(odd ? v11 : v10);
            a[2] = f2t(odd ? w01 : w00);
            a[3] = f2t(odd ? w11 : w10);
            int k = kt * 8;
            #pragma unroll
            for (int nt = 0; nt < 8; nt++) {
                uint32_t b[2];
                b[0] = f2t(Vb[(k + lq) * VP + nt * 8 + l4]);
                b[1] = f2t(Vb[(k + 4 + lq) * VP + nt * 8 + l4]);
                mma_tf32(o[nt], a, b);
            }
        }
        __syncthreads();
    }

    // Epilogue: write y [B,C,E], e = h*64 + d
    int h_ = bh & 15, b_ = bh >> 4;
    int q0 = qb * 64 + mrow + l4;
    float il0 = 1.0f / ls0, il1 = 1.0f / ls1;
    #pragma unroll
    for (int nt = 0; nt < 8; nt++) {
        int d = nt * 8 + lq * 2;
        size_t base = ((size_t)b_ * PC + q0) * PE + h_ * PHD + d;
        *(float2*)&g_y[base] = make_float2(o[nt][0] * il0, o[nt][1] * il0);
        *(float2*)&g_y[base + (size_t)8 * PE] =
            make_float2(o[nt][2] * il1, o[nt][3] * il1);
    }
}

// ---------------------------------------------------------------------------
extern "C" void kernel_launch(void* const* d_in, const int* in_sizes, int n_in,
                              void* d_out, int out_size)
{
    const float* x  = (const float*)d_in[0];
    const float* Wa = (const float*)d_in[1];
    const float* Wp = (const float*)d_in[2];
    float* out = (float*)d_out;

    size_t smemG = (size_t)(2 * ASZ + 2 * BSZ) * sizeof(float);     // 71680
    size_t smemA = (size_t)(QS_SZ + 2 * QS_SZ + 2 * VS_SZ) * sizeof(float); // 89088

    cudaFuncSetAttribute(gemm_tf32<PN3, 0>,
                         cudaFuncAttributeMaxDynamicSharedMemorySize, (int)smemG);
    cudaFuncSetAttribute(gemm_tf32<PE, 1>,
                         cudaFuncAttributeMaxDynamicSharedMemorySize, (int)smemG);
    cudaFuncSetAttribute(attn_tf32,
                         cudaFuncAttributeMaxDynamicSharedMemorySize, (int)smemA);

    gemm_tf32<PN3, 0><<<dim3(PN3 / 128, PM / 128), 256, smemG>>>(x, Wa, nullptr);
    attn_tf32<<<dim3(PC / 64, PB * PH), 128, smemA>>>();
    gemm_tf32<PE, 1><<<dim3(PE / 128, PM / 128), 256, smemG>>>(nullptr, Wp, out);
}